// round 15
// baseline (speedup 1.0000x reference)
#include <cuda_runtime.h>
#include <cuda_bf16.h>
#include <math.h>
#include <stdint.h>

// Problem constants
#define Bq   2
#define Tq   2048
#define Dq   1024      // D_MODEL == DI
#define DSq  16
#define Kq   4
#define ROWS (Bq*Tq)   // 4096
#define NCq  64        // scan chunks per sequence
#define Lq   (Tq/NCq)  // 32 timesteps per chunk
#define NBC  1152      // dt GEMM padded N (1024 dt + 16 B + 16 C + 96 pad)

// ---------------- scratch (device globals; no allocation allowed) ----------
__device__ float g_xz[ROWS * 2 * Dq];    // xn @ W_in
__device__ float g_xs[ROWS * Dq];        // conv + silu (fp32, for scan)
__device__ float g_dt[ROWS * Dq];        // softplus(xs @ dt_w + dt_b)
__device__ float g_decay[ROWS * Dq];     // per-step decay exp(min(dt*A,0))
__device__ float g_Bm[ROWS * DSq];
__device__ float g_Cm[ROWS * DSq];
__device__ float g_hend  [Bq * NCq * Dq * DSq];
__device__ float g_hstart[Bq * NCq * Dq * DSq];
__device__ float g_P     [Bq * NCq * Dq];
__device__ float g_negA  [Dq];           // -exp(log_A)
// bf16 split buffers (reused between GEMMs; single stream => sequential)
__device__ __nv_bfloat16 g_ah[ROWS * Dq];      // activation hi
__device__ __nv_bfloat16 g_al[ROWS * Dq];      // activation lo
__device__ __nv_bfloat16 g_wh[2 * Dq * Dq];    // transposed weight hi [N,K]
__device__ __nv_bfloat16 g_wl[2 * Dq * Dq];    // transposed weight lo [N,K]

// ---------------- math helpers ----------------
__device__ __forceinline__ float softplus_fast(float v) {
    if (v > 20.f)  return v;
    if (v < -15.f) return __expf(v);
    return __logf(1.f + __expf(v));
}
__device__ __forceinline__ float siluf(float v) {
    return __fdividef(v, 1.f + __expf(-v));
}
__device__ __forceinline__ void split_bf16(float v, __nv_bfloat16& h, __nv_bfloat16& l) {
    h = __float2bfloat16(v);
    l = __float2bfloat16(v - __bfloat162float(h));
}

// ---------------- PTX helpers (sm_80+ baseline; no 'a' features) ----------
__device__ __forceinline__ uint32_t smem_u32(const void* p) {
    uint32_t a;
    asm("{ .reg .u64 t; cvta.to.shared.u64 t, %1; cvt.u32.u64 %0, t; }"
        : "=r"(a) : "l"(p));
    return a;
}
__device__ __forceinline__ void cp16(uint32_t dst, const void* src) {
    asm volatile("cp.async.cg.shared.global [%0], [%1], 16;"
                 :: "r"(dst), "l"(src));
}
__device__ __forceinline__ void ldm_x4(uint32_t& r0, uint32_t& r1,
                                       uint32_t& r2, uint32_t& r3, uint32_t a) {
    asm volatile("ldmatrix.sync.aligned.m8n8.x4.shared.b16 {%0,%1,%2,%3}, [%4];"
                 : "=r"(r0), "=r"(r1), "=r"(r2), "=r"(r3) : "r"(a));
}
__device__ __forceinline__ void mma16816(float& c0, float& c1, float& c2, float& c3,
                                         uint32_t a0, uint32_t a1, uint32_t a2, uint32_t a3,
                                         uint32_t b0, uint32_t b1) {
    asm volatile("mma.sync.aligned.m16n8k16.row.col.f32.bf16.bf16.f32 "
                 "{%0,%1,%2,%3}, {%4,%5,%6,%7}, {%8,%9}, {%0,%1,%2,%3};"
                 : "+f"(c0), "+f"(c1), "+f"(c2), "+f"(c3)
                 : "r"(a0), "r"(a1), "r"(a2), "r"(a3), "r"(b0), "r"(b1));
}

// ---------------- weight [K,N] -> transposed hi/lo bf16 [N,K] --------------
__global__ void __launch_bounds__(256) convert_wt_kernel(
    const float* __restrict__ W, __nv_bfloat16* __restrict__ hiT,
    __nv_bfloat16* __restrict__ loT, int K, int N)
{
    __shared__ float sm[32][33];
    int n0 = blockIdx.x * 32, k0 = blockIdx.y * 32;
    int tx = threadIdx.x & 31, ty = threadIdx.x >> 5;
    #pragma unroll
    for (int i = 0; i < 4; i++)
        sm[ty + i * 8][tx] = W[(long)(k0 + ty + i * 8) * N + n0 + tx];
    __syncthreads();
    #pragma unroll
    for (int i = 0; i < 4; i++) {
        int n = n0 + ty + i * 8, k = k0 + tx;
        float v = sm[tx][ty + i * 8];
        __nv_bfloat16 h, l;
        split_bf16(v, h, l);
        hiT[(long)n * K + k] = h;
        loT[(long)n * K + k] = l;
    }
}

// ---- B_w/C_w [1024,16] -> rows 1024..1055 of wh/wl; rows 1056..1151 zero --
// also precomputes negA = -exp(log_A)
__global__ void __launch_bounds__(256) bc_wt_kernel(
    const float* __restrict__ Bw, const float* __restrict__ Cw,
    const float* __restrict__ log_A,
    __nv_bfloat16* __restrict__ hiT, __nv_bfloat16* __restrict__ loT,
    float* __restrict__ negA)
{
    int idx = blockIdx.x * 256 + threadIdx.x;  // 0 .. 128*1024-1
    int row = idx >> 10;                        // 0..127
    int k   = idx & (Dq - 1);
    if (row == 0) negA[k] = -expf(log_A[k]);
    float v = 0.f;
    if (row < 32) {
        const float* W = (row < 16) ? Bw : Cw;
        v = W[k * DSq + (row & 15)];
    }
    __nv_bfloat16 h, l;
    split_bf16(v, h, l);
    long o = (long)(Dq + row) * Dq + k;
    hiT[o] = h;
    loT[o] = l;
}

// ---------------- mma.sync bf16 GEMM: C[M,N] = A[M,K] * W[K,N] -------------
// 256x128 CTA tile, 512 threads / 16 warps (4m x 4n, 64x32 per warp) for
// 4 warps/SMSP latency hiding at 1 CTA/SM.
// 3-stage cp.async pipeline, ONE __syncthreads per K-iter.
// Unpadded 64B rows + chunk permutation (16B-aligned, conflict-free).
// acc += Ah*Bh + Ah*Bl + Al*Bh (fp32 register accumulators).
#define BKg     32
#define TILE_A  (256 * 64)             // 16384 B per A array (256 rows)
#define TILE_W  (128 * 64)             // 8192 B per B array (128 rows)
#define STAGE_B (2 * TILE_A + 2 * TILE_W)   // 49152 B per stage
#define GSM_SZ  (3 * STAGE_B)          // 147456 B, 3-stage, 1 CTA/SM
#define GT      512                    // GEMM threads

// physical byte offset of 16B chunk c (0..3) in row
__device__ __forceinline__ uint32_t perm_off(int row, int c) {
    return (uint32_t)(row * 64 + (((c + (row >> 1)) & 3) << 4));
}

__device__ __forceinline__ void stage_loads(
    uint32_t sbase, const __nv_bfloat16* __restrict__ Ah,
    const __nv_bfloat16* __restrict__ Al, const __nv_bfloat16* __restrict__ Bh,
    const __nv_bfloat16* __restrict__ Bl, int bm, int bn, int K, int k0, int tid)
{
    // A: 256 rows x 4 chunks = 1024 cp16 per array
    #pragma unroll
    for (int arr = 0; arr < 2; arr++) {
        const __nv_bfloat16* s = arr ? Al : Ah;
        #pragma unroll
        for (int i = 0; i < 2; i++) {
            int idx = tid + i * GT;           // 0..1023
            int row = idx >> 2, seg = idx & 3;
            cp16(sbase + arr * TILE_A + perm_off(row, seg),
                 s + (long)(bm + row) * K + k0 + seg * 8);
        }
    }
    // B: 128 rows x 4 chunks = 512 cp16 per array (one pass of 512 threads)
    #pragma unroll
    for (int arr = 0; arr < 2; arr++) {
        const __nv_bfloat16* s = arr ? Bl : Bh;
        int idx = tid;                        // 0..511
        int row = idx >> 2, seg = idx & 3;
        cp16(sbase + 2 * TILE_A + arr * TILE_W + perm_off(row, seg),
             s + (long)(bn + row) * K + k0 + seg * 8);
    }
    asm volatile("cp.async.commit_group;" ::: "memory");
}

template<int EPI>
__global__ void __launch_bounds__(GT) gemm_mma(
    const __nv_bfloat16* __restrict__ Ah, const __nv_bfloat16* __restrict__ Al,
    const __nv_bfloat16* __restrict__ Bh, const __nv_bfloat16* __restrict__ Bl,
    float* __restrict__ C, int M, int N, int K, int ldc,
    const float* __restrict__ bias, const float* __restrict__ resid,
    float* __restrict__ BmP, float* __restrict__ CmP)
{
    extern __shared__ char smem[];
    uint32_t sb = smem_u32(smem);
    int tid = threadIdx.x, wid = tid >> 5, lane = tid & 31;
    int bm = blockIdx.y * 256, bn = blockIdx.x * 128;
    int wm = (wid >> 2) * 64;         // warp m offset: 0/64/128/192
    int wn = (wid & 3) * 32;          // warp n offset: 0/32/64/96

    float acc[4][4][4];
    #pragma unroll
    for (int i = 0; i < 4; i++)
        #pragma unroll
        for (int j = 0; j < 4; j++)
            #pragma unroll
            for (int r = 0; r < 4; r++) acc[i][j][r] = 0.f;

    // prologue: stages for kt=0 and kt=1
    stage_loads(sb,           Ah, Al, Bh, Bl, bm, bn, K, 0,   tid);
    stage_loads(sb + STAGE_B, Ah, Al, Bh, Bl, bm, bn, K, BKg, tid);

    const int NK = K / BKg;           // K/32
    int a_row = lane & 15;
    int a_cseg = (lane >> 4);         // 0/1 -> chunk lsb
    int b_row = (lane & 7) + ((lane >> 4) * 8);
    int b_cseg = ((lane >> 3) & 1);

    for (int kt = 0; kt < NK; kt++) {
        // stage kt arrived (pending: kt, kt+1 -> leave <=1)
        asm volatile("cp.async.wait_group 1;" ::: "memory");
        __syncthreads();   // all warps finished reading buffer (kt+2)%3 at kt-1

        // issue loads for kt+2 into buffer (kt+2)%3
        if (kt + 2 < NK)
            stage_loads(sb + ((kt + 2) % 3) * STAGE_B, Ah, Al, Bh, Bl,
                        bm, bn, K, (kt + 2) * BKg, tid);
        else
            asm volatile("cp.async.commit_group;" ::: "memory");

        uint32_t stg = sb + (kt % 3) * STAGE_B;
        #pragma unroll
        for (int ks = 0; ks < 2; ks++) {
            int cA = ks * 2 + a_cseg;          // logical chunk 0..3
            uint32_t aH[4][4], aL[4][4];
            #pragma unroll
            for (int mi = 0; mi < 4; mi++) {
                int r = wm + mi * 16 + a_row;
                uint32_t off = perm_off(r, cA);
                ldm_x4(aH[mi][0], aH[mi][1], aH[mi][2], aH[mi][3], stg + off);
                ldm_x4(aL[mi][0], aL[mi][1], aL[mi][2], aL[mi][3],
                       stg + TILE_A + off);
            }
            #pragma unroll
            for (int nb = 0; nb < 2; nb++) {   // two n16 groups of warp n32
                int rr = wn + nb * 16 + b_row;
                int cB = ks * 2 + b_cseg;
                uint32_t off = perm_off(rr, cB);
                uint32_t bH[4], bL[4];
                ldm_x4(bH[0], bH[1], bH[2], bH[3],
                       stg + 2 * TILE_A + off);
                ldm_x4(bL[0], bL[1], bL[2], bL[3],
                       stg + 2 * TILE_A + TILE_W + off);
                #pragma unroll
                for (int mi = 0; mi < 4; mi++) {
                    #pragma unroll
                    for (int h = 0; h < 2; h++) {
                        int nj = nb * 2 + h;
                        float* c = acc[mi][nj];
                        mma16816(c[0], c[1], c[2], c[3],
                                 aH[mi][0], aH[mi][1], aH[mi][2], aH[mi][3],
                                 bH[2*h], bH[2*h+1]);
                        mma16816(c[0], c[1], c[2], c[3],
                                 aH[mi][0], aH[mi][1], aH[mi][2], aH[mi][3],
                                 bL[2*h], bL[2*h+1]);
                        mma16816(c[0], c[1], c[2], c[3],
                                 aL[mi][0], aL[mi][1], aL[mi][2], aL[mi][3],
                                 bH[2*h], bH[2*h+1]);
                    }
                }
            }
        }
    }

    // ---- epilogue: fragment layout -> direct float2 stores
    int g  = lane >> 2;
    int tg = lane & 3;
    #pragma unroll
    for (int mi = 0; mi < 4; mi++) {
        #pragma unroll
        for (int nj = 0; nj < 4; nj++) {
            int n0 = bn + wn + nj * 8 + tg * 2;
            float* c = acc[mi][nj];
            #pragma unroll
            for (int rh = 0; rh < 2; rh++) {
                int m = bm + wm + mi * 16 + g + rh * 8;
                float v0 = c[rh * 2 + 0], v1 = c[rh * 2 + 1];
                if (EPI == 0) {
                    *(float2*)(C + (long)m * ldc + n0) = make_float2(v0, v1);
                } else if (EPI == 1) {
                    if (n0 < Dq) {
                        v0 = softplus_fast(v0 + bias[n0]);
                        v1 = softplus_fast(v1 + bias[n0 + 1]);
                        *(float2*)(C + (long)m * ldc + n0) = make_float2(v0, v1);
                    } else if (n0 < Dq + DSq) {
                        *(float2*)(BmP + (long)m * DSq + (n0 - Dq)) =
                            make_float2(v0, v1);
                    } else if (n0 < Dq + 2 * DSq) {
                        *(float2*)(CmP + (long)m * DSq + (n0 - Dq - DSq)) =
                            make_float2(v0, v1);
                    }
                } else {  // EPI == 2
                    const float* rp = resid + (long)m * ldc + n0;
                    *(float2*)(C + (long)m * ldc + n0) =
                        make_float2(v0 + rp[0], v1 + rp[1]);
                }
            }
        }
    }
}

// ---------------- LayerNorm + bf16 split (fused): one block per row --------
__global__ void __launch_bounds__(256) ln_split_kernel(
    const float* __restrict__ x, const float* __restrict__ g,
    const float* __restrict__ b, __nv_bfloat16* __restrict__ ah,
    __nv_bfloat16* __restrict__ al)
{
    int row = blockIdx.x;
    int tid = threadIdx.x;
    const float4* xr = (const float4*)(x + (long)row * Dq);
    float4 v = xr[tid];
    float s  = v.x + v.y + v.z + v.w;
    float sq = v.x*v.x + v.y*v.y + v.z*v.z + v.w*v.w;
    #pragma unroll
    for (int o = 16; o; o >>= 1) {
        s  += __shfl_xor_sync(0xffffffffu, s,  o);
        sq += __shfl_xor_sync(0xffffffffu, sq, o);
    }
    __shared__ float ss[8], ssq[8];
    if ((tid & 31) == 0) { ss[tid >> 5] = s; ssq[tid >> 5] = sq; }
    __syncthreads();
    float ts = 0.f, tq = 0.f;
    #pragma unroll
    for (int w = 0; w < 8; w++) { ts += ss[w]; tq += ssq[w]; }
    float mu  = ts * (1.f / Dq);
    float var = tq * (1.f / Dq) - mu * mu;
    float r   = rsqrtf(var + 1e-5f);
    float4 gg = ((const float4*)g)[tid];
    float4 bb = ((const float4*)b)[tid];
    float o0 = (v.x - mu) * r * gg.x + bb.x;
    float o1 = (v.y - mu) * r * gg.y + bb.y;
    float o2 = (v.z - mu) * r * gg.z + bb.z;
    float o3 = (v.w - mu) * r * gg.w + bb.w;
    __nv_bfloat16 h0, l0, h1, l1, h2, l2, h3, l3;
    split_bf16(o0, h0, l0); split_bf16(o1, h1, l1);
    split_bf16(o2, h2, l2); split_bf16(o3, h3, l3);
    long i2 = (long)row * (Dq / 2) + tid * 2;
    ((__nv_bfloat162*)ah)[i2]     = __halves2bfloat162(h0, h1);
    ((__nv_bfloat162*)ah)[i2 + 1] = __halves2bfloat162(h2, h3);
    ((__nv_bfloat162*)al)[i2]     = __halves2bfloat162(l0, l1);
    ((__nv_bfloat162*)al)[i2 + 1] = __halves2bfloat162(l2, l3);
}

// ---------------- Conv(K=4 causal) + SiLU + bf16 split: 1 block per row ----
__global__ void __launch_bounds__(256) conv_silu_split(
    const float* __restrict__ xz, const float* __restrict__ w,
    const float* __restrict__ cb, float* __restrict__ xs,
    __nv_bfloat16* __restrict__ ah, __nv_bfloat16* __restrict__ al)
{
    int row = blockIdx.x;                  // b*Tq + t
    int t   = row & (Tq - 1);
    int tid = threadIdx.x;
    int d0  = tid * 4;

    const float4* wp = (const float4*)(w + d0 * Kq);
    float4 w0 = wp[0], w1 = wp[1], w2 = wp[2], w3 = wp[3];

    float4 acc = *(const float4*)(cb + d0);
    #pragma unroll
    for (int k = 0; k < Kq; k++) {
        int tt = t - (Kq - 1) + k;
        if (tt >= 0) {
            const float* src = xz + ((long)(row - (Kq - 1) + k)) * (2 * Dq) + d0;
            float4 xv = *(const float4*)src;
            float t0 = (k == 0) ? w0.x : (k == 1) ? w0.y : (k == 2) ? w0.z : w0.w;
            float t1 = (k == 0) ? w1.x : (k == 1) ? w1.y : (k == 2) ? w1.z : w1.w;
            float t2 = (k == 0) ? w2.x : (k == 1) ? w2.y : (k == 2) ? w2.z : w2.w;
            float t3 = (k == 0) ? w3.x : (k == 1) ? w3.y : (k == 2) ? w3.z : w3.w;
            acc.x += t0 * xv.x;
            acc.y += t1 * xv.y;
            acc.z += t2 * xv.z;
            acc.w += t3 * xv.w;
        }
    }
    float s0 = siluf(acc.x), s1 = siluf(acc.y);
    float s2 = siluf(acc.z), s3 = siluf(acc.w);

    *(float4*)(xs + (long)row * Dq + d0) = make_float4(s0, s1, s2, s3);
    __nv_bfloat16 h0, l0, h1, l1, h2, l2, h3, l3;
    split_bf16(s0, h0, l0); split_bf16(s1, h1, l1);
    split_bf16(s2, h2, l2); split_bf16(s3, h3, l3);
    long i2 = (long)row * (Dq / 2) + tid * 2;
    ((__nv_bfloat162*)ah)[i2]     = __halves2bfloat162(h0, h1);
    ((__nv_bfloat162*)ah)[i2 + 1] = __halves2bfloat162(h2, h3);
    ((__nv_bfloat162*)al)[i2]     = __halves2bfloat162(l0, l1);
    ((__nv_bfloat162*)al)[i2 + 1] = __halves2bfloat162(l2, l3);
}

// ---------------- Chunked parallel selective scan ---------------------------
// Pass 1: local scan from h=0; emit end state, decay product, per-step decay
__global__ void __launch_bounds__(256) scan_pass1(
    const float* __restrict__ xs, const float* __restrict__ dt,
    const float* __restrict__ Bm, const float* __restrict__ negA,
    float* __restrict__ hend, float* __restrict__ Pp,
    float* __restrict__ decay)
{
    int blk = blockIdx.x;
    int b   = blk >> 8;
    int rem = blk & 255;
    int c   = rem >> 2;
    int d   = ((rem & 3) << 8) + threadIdx.x;
    float A = negA[d];

    __shared__ float Bs[Lq][DSq];
    for (int i = threadIdx.x; i < Lq * DSq; i += 256)
        Bs[i >> 4][i & 15] = Bm[((long)(b * Tq + c * Lq)) * DSq + i];
    __syncthreads();

    float h[DSq];
    #pragma unroll
    for (int s = 0; s < DSq; s++) h[s] = 0.f;
    float slog = 0.f;

    #pragma unroll 4
    for (int tt = 0; tt < Lq; tt++) {
        long row = (long)(b * Tq + c * Lq + tt);
        float xv  = xs[row * Dq + d];
        float dtv = dt[row * Dq + d];
        float e = fminf(dtv * A, 0.f);
        slog += e;
        float a = __expf(e);
        decay[row * Dq + d] = a;
        float u = dtv * xv;
        #pragma unroll
        for (int s = 0; s < DSq; s++) h[s] = h[s] * a + u * Bs[tt][s];
    }

    long base = (((long)(b * NCq + c)) * Dq + d) * DSq;
    #pragma unroll
    for (int s = 0; s < DSq; s++) hend[base + s] = h[s];
    Pp[((long)(b * NCq + c)) * Dq + d] = __expf(slog);
}

__global__ void __launch_bounds__(256) scan_pass2(
    const float* __restrict__ hend, const float* __restrict__ Pp,
    float* __restrict__ hstart)
{
    int idx = blockIdx.x * 256 + threadIdx.x;
    int s = idx & 15;
    int d = (idx >> 4) & (Dq - 1);
    int b = idx >> 14;
    float hs = 0.f;
    for (int c = 0; c < NCq; c++) {
        long base = (((long)(b * NCq + c)) * Dq + d) * DSq + s;
        hstart[base] = hs;
        float P = Pp[((long)(b * NCq + c)) * Dq + d];
        hs = P * hs + hend[base];
    }
}

// Pass 3: re-run chunk from known start using stored decay; gate; emit split y
__global__ void __launch_bounds__(256) scan_pass3(
    const float* __restrict__ xs, const float* __restrict__ dt,
    const float* __restrict__ Bm, const float* __restrict__ Cm,
    const float* __restrict__ decay, const float* __restrict__ Dp,
    const float* __restrict__ xz, const float* __restrict__ hstart,
    __nv_bfloat16* __restrict__ yh, __nv_bfloat16* __restrict__ yl)
{
    int blk = blockIdx.x;
    int b   = blk >> 8;
    int rem = blk & 255;
    int c   = rem >> 2;
    int d   = ((rem & 3) << 8) + threadIdx.x;
    float Dv = Dp[d];

    __shared__ float Bs[Lq][DSq];
    __shared__ float Cs[Lq][DSq];
    for (int i = threadIdx.x; i < Lq * DSq; i += 256) {
        Bs[i >> 4][i & 15] = Bm[((long)(b * Tq + c * Lq)) * DSq + i];
        Cs[i >> 4][i & 15] = Cm[((long)(b * Tq + c * Lq)) * DSq + i];
    }
    __syncthreads();

    float h[DSq];
    long base = (((long)(b * NCq + c)) * Dq + d) * DSq;
    #pragma unroll
    for (int s = 0; s < DSq; s++) h[s] = hstart[base + s];

    #pragma unroll 4
    for (int tt = 0; tt < Lq; tt++) {
        long row = (long)(b * Tq + c * Lq + tt);
        float xv  = xs[row * Dq + d];
        float dtv = dt[row * Dq + d];
        float a   = decay[row * Dq + d];
        float u = dtv * xv;
        float acc = 0.f;
        #pragma unroll
        for (int s = 0; s < DSq; s++) {
            h[s] = h[s] * a + u * Bs[tt][s];
            acc += h[s] * Cs[tt][s];
        }
        float zv = xz[row * (2 * Dq) + Dq + d];
        float yv = (acc + xv * Dv) * siluf(zv);
        __nv_bfloat16 hh, ll;
        split_bf16(yv, hh, ll);
        yh[row * Dq + d] = hh;
        yl[row * Dq + d] = ll;
    }
}

// ---------------- launch ----------------------------------------------------
extern "C" void kernel_launch(void* const* d_in, const int* in_sizes, int n_in,
                              void* d_out, int out_size)
{
    const float* x      = (const float*)d_in[0];
    const float* ln_g   = (const float*)d_in[1];
    const float* ln_b   = (const float*)d_in[2];
    const float* W_in   = (const float*)d_in[3];
    const float* conv_w = (const float*)d_in[4];
    const float* conv_b = (const float*)d_in[5];
    const float* dt_w   = (const float*)d_in[6];
    const float* dt_b   = (const float*)d_in[7];
    const float* B_w    = (const float*)d_in[8];
    const float* C_w    = (const float*)d_in[9];
    const float* log_A  = (const float*)d_in[10];
    const float* D_par  = (const float*)d_in[11];
    const float* W_out  = (const float*)d_in[12];
    float* out = (float*)d_out;

    float *xz, *xs, *dt, *dc, *Bm, *Cm, *he, *hs, *Pp, *nA;
    __nv_bfloat16 *ah, *al, *wh, *wl;
    cudaGetSymbolAddress((void**)&xz, g_xz);
    cudaGetSymbolAddress((void**)&xs, g_xs);
    cudaGetSymbolAddress((void**)&dt, g_dt);
    cudaGetSymbolAddress((void**)&dc, g_decay);
    cudaGetSymbolAddress((void**)&Bm, g_Bm);
    cudaGetSymbolAddress((void**)&Cm, g_Cm);
    cudaGetSymbolAddress((void**)&he, g_hend);
    cudaGetSymbolAddress((void**)&hs, g_hstart);
    cudaGetSymbolAddress((void**)&Pp, g_P);
    cudaGetSymbolAddress((void**)&nA, g_negA);
    cudaGetSymbolAddress((void**)&ah, g_ah);
    cudaGetSymbolAddress((void**)&al, g_al);
    cudaGetSymbolAddress((void**)&wh, g_wh);
    cudaGetSymbolAddress((void**)&wl, g_wl);

    cudaFuncSetAttribute(gemm_mma<0>, cudaFuncAttributeMaxDynamicSharedMemorySize, GSM_SZ);
    cudaFuncSetAttribute(gemm_mma<1>, cudaFuncAttributeMaxDynamicSharedMemorySize, GSM_SZ);
    cudaFuncSetAttribute(gemm_mma<2>, cudaFuncAttributeMaxDynamicSharedMemorySize, GSM_SZ);

    // 1. LayerNorm + bf16 split (fused)
    ln_split_kernel<<<ROWS, 256>>>(x, ln_g, ln_b, ah, al);

    // 2. xz = xn @ W_in   [4096,1024]x[1024,2048]
    convert_wt_kernel<<<dim3(2 * Dq / 32, Dq / 32), 256>>>(W_in, wh, wl, Dq, 2 * Dq);
    gemm_mma<0><<<dim3(2 * Dq / 128, ROWS / 256), GT, GSM_SZ>>>(
        ah, al, wh, wl, xz, ROWS, 2 * Dq, Dq, 2 * Dq, nullptr, nullptr,
        nullptr, nullptr);

    // 3. conv + silu + bf16 split (fused)
    conv_silu_split<<<ROWS, 256>>>(xz, conv_w, conv_b, xs, ah, al);

    // 4. combined GEMM: [dt | Bm | Cm] = xs @ [dt_w | B_w | C_w] (N=1152)
    convert_wt_kernel<<<dim3(Dq / 32, Dq / 32), 256>>>(dt_w, wh, wl, Dq, Dq);
    bc_wt_kernel<<<(128 * Dq) / 256, 256>>>(B_w, C_w, log_A, wh, wl, nA);
    gemm_mma<1><<<dim3(NBC / 128, ROWS / 256), GT, GSM_SZ>>>(
        ah, al, wh, wl, dt, ROWS, NBC, Dq, Dq, dt_b, nullptr, Bm, Cm);

    // 5. chunked parallel selective scan + gate (emits split y)
    scan_pass1<<<Bq * NCq * (Dq / 256), 256>>>(xs, dt, Bm, nA, he, Pp, dc);
    scan_pass2<<<(Bq * Dq * DSq) / 256, 256>>>(he, Pp, hs);
    scan_pass3<<<Bq * NCq * (Dq / 256), 256>>>(xs, dt, Bm, Cm, dc, D_par,
                                               xz, hs, ah, al);

    // 6. out = residual + y @ W_out
    convert_wt_kernel<<<dim3(Dq / 32, Dq / 32), 256>>>(W_out, wh, wl, Dq, Dq);
    gemm_mma<2><<<dim3(Dq / 128, ROWS / 256), GT, GSM_SZ>>>(
        ah, al, wh, wl, out, ROWS, Dq, Dq, Dq, nullptr, x, nullptr, nullptr);
}

// round 16
// speedup vs baseline: 1.5073x; 1.5073x over previous
#include <cuda_runtime.h>
#include <cuda_bf16.h>
#include <math.h>
#include <stdint.h>

// Problem constants
#define Bq   2
#define Tq   2048
#define Dq   1024      // D_MODEL == DI
#define DSq  16
#define Kq   4
#define ROWS (Bq*Tq)   // 4096
#define NCq  64        // scan chunks per sequence
#define Lq   (Tq/NCq)  // 32 timesteps per chunk
#define NBC  1152      // dt GEMM padded N (1024 dt + 16 B + 16 C + 96 pad)

// ---------------- scratch (device globals; no allocation allowed) ----------
__device__ float g_xz[ROWS * 2 * Dq];    // xn @ W_in
__device__ float g_xs[ROWS * Dq];        // conv + silu (fp32, for scan)
__device__ float g_dt[ROWS * Dq];        // softplus(xs @ dt_w + dt_b)
__device__ float g_decay[ROWS * Dq];     // per-step decay exp(min(dt*A,0))
__device__ float g_Bm[ROWS * DSq];
__device__ float g_Cm[ROWS * DSq];
__device__ float g_hend  [Bq * NCq * Dq * DSq];
__device__ float g_hstart[Bq * NCq * Dq * DSq];
__device__ float g_P     [Bq * NCq * Dq];
__device__ float g_negA  [Dq];           // -exp(log_A)
// bf16 split buffers (reused between GEMMs; single stream => sequential)
__device__ __nv_bfloat16 g_ah[ROWS * Dq];      // activation hi
__device__ __nv_bfloat16 g_al[ROWS * Dq];      // activation lo
__device__ __nv_bfloat16 g_wh[2 * Dq * Dq];    // transposed weight hi [N,K]
__device__ __nv_bfloat16 g_wl[2 * Dq * Dq];    // transposed weight lo [N,K]

// ---------------- math helpers ----------------
__device__ __forceinline__ float softplus_fast(float v) {
    if (v > 20.f)  return v;
    if (v < -15.f) return __expf(v);
    return __logf(1.f + __expf(v));
}
__device__ __forceinline__ float siluf(float v) {
    return __fdividef(v, 1.f + __expf(-v));
}
__device__ __forceinline__ void split_bf16(float v, __nv_bfloat16& h, __nv_bfloat16& l) {
    h = __float2bfloat16(v);
    l = __float2bfloat16(v - __bfloat162float(h));
}

// ---------------- PTX helpers (sm_80+ baseline; no 'a' features) ----------
__device__ __forceinline__ uint32_t smem_u32(const void* p) {
    uint32_t a;
    asm("{ .reg .u64 t; cvta.to.shared.u64 t, %1; cvt.u32.u64 %0, t; }"
        : "=r"(a) : "l"(p));
    return a;
}
__device__ __forceinline__ void cp16(uint32_t dst, const void* src) {
    asm volatile("cp.async.cg.shared.global [%0], [%1], 16;"
                 :: "r"(dst), "l"(src));
}
__device__ __forceinline__ void ldm_x4(uint32_t& r0, uint32_t& r1,
                                       uint32_t& r2, uint32_t& r3, uint32_t a) {
    asm volatile("ldmatrix.sync.aligned.m8n8.x4.shared.b16 {%0,%1,%2,%3}, [%4];"
                 : "=r"(r0), "=r"(r1), "=r"(r2), "=r"(r3) : "r"(a));
}
__device__ __forceinline__ void mma16816(float& c0, float& c1, float& c2, float& c3,
                                         uint32_t a0, uint32_t a1, uint32_t a2, uint32_t a3,
                                         uint32_t b0, uint32_t b1) {
    asm volatile("mma.sync.aligned.m16n8k16.row.col.f32.bf16.bf16.f32 "
                 "{%0,%1,%2,%3}, {%4,%5,%6,%7}, {%8,%9}, {%0,%1,%2,%3};"
                 : "+f"(c0), "+f"(c1), "+f"(c2), "+f"(c3)
                 : "r"(a0), "r"(a1), "r"(a2), "r"(a3), "r"(b0), "r"(b1));
}

// ---------------- weight [K,N] -> transposed hi/lo bf16 [N,K] --------------
__global__ void __launch_bounds__(256) convert_wt_kernel(
    const float* __restrict__ W, __nv_bfloat16* __restrict__ hiT,
    __nv_bfloat16* __restrict__ loT, int K, int N)
{
    __shared__ float sm[32][33];
    int n0 = blockIdx.x * 32, k0 = blockIdx.y * 32;
    int tx = threadIdx.x & 31, ty = threadIdx.x >> 5;
    #pragma unroll
    for (int i = 0; i < 4; i++)
        sm[ty + i * 8][tx] = W[(long)(k0 + ty + i * 8) * N + n0 + tx];
    __syncthreads();
    #pragma unroll
    for (int i = 0; i < 4; i++) {
        int n = n0 + ty + i * 8, k = k0 + tx;
        float v = sm[tx][ty + i * 8];
        __nv_bfloat16 h, l;
        split_bf16(v, h, l);
        hiT[(long)n * K + k] = h;
        loT[(long)n * K + k] = l;
    }
}

// ---- B_w/C_w [1024,16] -> rows 1024..1055 of wh/wl; rows 1056..1151 zero --
// also precomputes negA = -exp(log_A)
__global__ void __launch_bounds__(256) bc_wt_kernel(
    const float* __restrict__ Bw, const float* __restrict__ Cw,
    const float* __restrict__ log_A,
    __nv_bfloat16* __restrict__ hiT, __nv_bfloat16* __restrict__ loT,
    float* __restrict__ negA)
{
    int idx = blockIdx.x * 256 + threadIdx.x;  // 0 .. 128*1024-1
    int row = idx >> 10;                        // 0..127
    int k   = idx & (Dq - 1);
    if (row == 0) negA[k] = -expf(log_A[k]);
    float v = 0.f;
    if (row < 32) {
        const float* W = (row < 16) ? Bw : Cw;
        v = W[k * DSq + (row & 15)];
    }
    __nv_bfloat16 h, l;
    split_bf16(v, h, l);
    long o = (long)(Dq + row) * Dq + k;
    hiT[o] = h;
    loT[o] = l;
}

// ---------------- mma.sync bf16 GEMM: C[M,N] = A[M,K] * W[K,N] -------------
// 256x128 CTA tile, 256 threads / 8 warps (4m x 2n, 64x64 per warp).
// 3-stage cp.async pipeline, ONE __syncthreads per K-iter, 1 CTA/SM.
// Unpadded 64B rows + chunk permutation (16B-aligned, conflict-free).
// acc += Ah*Bh + Ah*Bl + Al*Bh (fp32 register accumulators).
#define BKg     32
#define TILE_A  (256 * 64)             // 16384 B per A array (256 rows)
#define TILE_W  (128 * 64)             // 8192 B per B array (128 rows)
#define STAGE_B (2 * TILE_A + 2 * TILE_W)   // 49152 B per stage
#define GSM_SZ  (3 * STAGE_B)          // 147456 B, 3-stage, 1 CTA/SM

// physical byte offset of 16B chunk c (0..3) in row
__device__ __forceinline__ uint32_t perm_off(int row, int c) {
    return (uint32_t)(row * 64 + (((c + (row >> 1)) & 3) << 4));
}

__device__ __forceinline__ void stage_loads(
    uint32_t sbase, const __nv_bfloat16* __restrict__ Ah,
    const __nv_bfloat16* __restrict__ Al, const __nv_bfloat16* __restrict__ Bh,
    const __nv_bfloat16* __restrict__ Bl, int bm, int bn, int K, int k0, int tid)
{
    // A: 256 rows x 4 chunks = 1024 cp16 per array
    #pragma unroll
    for (int arr = 0; arr < 2; arr++) {
        const __nv_bfloat16* s = arr ? Al : Ah;
        #pragma unroll
        for (int i = 0; i < 4; i++) {
            int idx = tid + i * 256;          // 0..1023
            int row = idx >> 2, seg = idx & 3;
            cp16(sbase + arr * TILE_A + perm_off(row, seg),
                 s + (long)(bm + row) * K + k0 + seg * 8);
        }
    }
    // B: 128 rows x 4 chunks = 512 cp16 per array
    #pragma unroll
    for (int arr = 0; arr < 2; arr++) {
        const __nv_bfloat16* s = arr ? Bl : Bh;
        #pragma unroll
        for (int i = 0; i < 2; i++) {
            int idx = tid + i * 256;          // 0..511
            int row = idx >> 2, seg = idx & 3;
            cp16(sbase + 2 * TILE_A + arr * TILE_W + perm_off(row, seg),
                 s + (long)(bn + row) * K + k0 + seg * 8);
        }
    }
    asm volatile("cp.async.commit_group;" ::: "memory");
}

template<int EPI>
__global__ void __launch_bounds__(256) gemm_mma(
    const __nv_bfloat16* __restrict__ Ah, const __nv_bfloat16* __restrict__ Al,
    const __nv_bfloat16* __restrict__ Bh, const __nv_bfloat16* __restrict__ Bl,
    float* __restrict__ C, int M, int N, int K, int ldc,
    const float* __restrict__ bias, const float* __restrict__ resid,
    float* __restrict__ BmP, float* __restrict__ CmP)
{
    extern __shared__ char smem[];
    uint32_t sb = smem_u32(smem);
    int tid = threadIdx.x, wid = tid >> 5, lane = tid & 31;
    int bm = blockIdx.y * 256, bn = blockIdx.x * 128;
    int wm = (wid >> 1) * 64;         // warp m offset: 0/64/128/192
    int wn = (wid & 1) * 64;          // warp n offset: 0/64

    float acc[4][8][4];
    #pragma unroll
    for (int i = 0; i < 4; i++)
        #pragma unroll
        for (int j = 0; j < 8; j++)
            #pragma unroll
            for (int r = 0; r < 4; r++) acc[i][j][r] = 0.f;

    // prologue: stages for kt=0 and kt=1
    stage_loads(sb,           Ah, Al, Bh, Bl, bm, bn, K, 0,   tid);
    stage_loads(sb + STAGE_B, Ah, Al, Bh, Bl, bm, bn, K, BKg, tid);

    const int NK = K / BKg;           // K/32
    int a_row = lane & 15;
    int a_cseg = (lane >> 4);         // 0/1 -> chunk lsb
    int b_row = (lane & 7) + ((lane >> 4) * 8);
    int b_cseg = ((lane >> 3) & 1);

    for (int kt = 0; kt < NK; kt++) {
        // stage kt arrived (pending: kt, kt+1 -> leave <=1)
        asm volatile("cp.async.wait_group 1;" ::: "memory");
        __syncthreads();   // all warps finished reading buffer (kt+2)%3 at kt-1

        // issue loads for kt+2 into buffer (kt+2)%3
        if (kt + 2 < NK)
            stage_loads(sb + ((kt + 2) % 3) * STAGE_B, Ah, Al, Bh, Bl,
                        bm, bn, K, (kt + 2) * BKg, tid);
        else
            asm volatile("cp.async.commit_group;" ::: "memory");

        uint32_t stg = sb + (kt % 3) * STAGE_B;
        #pragma unroll
        for (int ks = 0; ks < 2; ks++) {
            int cA = ks * 2 + a_cseg;          // logical chunk 0..3
            uint32_t aH[4][4], aL[4][4];
            #pragma unroll
            for (int mi = 0; mi < 4; mi++) {
                int r = wm + mi * 16 + a_row;
                uint32_t off = perm_off(r, cA);
                ldm_x4(aH[mi][0], aH[mi][1], aH[mi][2], aH[mi][3], stg + off);
                ldm_x4(aL[mi][0], aL[mi][1], aL[mi][2], aL[mi][3],
                       stg + TILE_A + off);
            }
            #pragma unroll
            for (int nb = 0; nb < 4; nb++) {   // four n16 groups of warp n64
                int rr = wn + nb * 16 + b_row;
                int cB = ks * 2 + b_cseg;
                uint32_t off = perm_off(rr, cB);
                uint32_t bH[4], bL[4];
                ldm_x4(bH[0], bH[1], bH[2], bH[3],
                       stg + 2 * TILE_A + off);
                ldm_x4(bL[0], bL[1], bL[2], bL[3],
                       stg + 2 * TILE_A + TILE_W + off);
                #pragma unroll
                for (int mi = 0; mi < 4; mi++) {
                    #pragma unroll
                    for (int h = 0; h < 2; h++) {
                        int nj = nb * 2 + h;
                        float* c = acc[mi][nj];
                        mma16816(c[0], c[1], c[2], c[3],
                                 aH[mi][0], aH[mi][1], aH[mi][2], aH[mi][3],
                                 bH[2*h], bH[2*h+1]);
                        mma16816(c[0], c[1], c[2], c[3],
                                 aH[mi][0], aH[mi][1], aH[mi][2], aH[mi][3],
                                 bL[2*h], bL[2*h+1]);
                        mma16816(c[0], c[1], c[2], c[3],
                                 aL[mi][0], aL[mi][1], aL[mi][2], aL[mi][3],
                                 bH[2*h], bH[2*h+1]);
                    }
                }
            }
        }
    }

    // ---- epilogue: fragment layout -> direct float2 stores
    int g  = lane >> 2;
    int tg = lane & 3;
    #pragma unroll
    for (int mi = 0; mi < 4; mi++) {
        #pragma unroll
        for (int nj = 0; nj < 8; nj++) {
            int n0 = bn + wn + nj * 8 + tg * 2;
            float* c = acc[mi][nj];
            #pragma unroll
            for (int rh = 0; rh < 2; rh++) {
                int m = bm + wm + mi * 16 + g + rh * 8;
                float v0 = c[rh * 2 + 0], v1 = c[rh * 2 + 1];
                if (EPI == 0) {
                    *(float2*)(C + (long)m * ldc + n0) = make_float2(v0, v1);
                } else if (EPI == 1) {
                    if (n0 < Dq) {
                        v0 = softplus_fast(v0 + bias[n0]);
                        v1 = softplus_fast(v1 + bias[n0 + 1]);
                        *(float2*)(C + (long)m * ldc + n0) = make_float2(v0, v1);
                    } else if (n0 < Dq + DSq) {
                        *(float2*)(BmP + (long)m * DSq + (n0 - Dq)) =
                            make_float2(v0, v1);
                    } else if (n0 < Dq + 2 * DSq) {
                        *(float2*)(CmP + (long)m * DSq + (n0 - Dq - DSq)) =
                            make_float2(v0, v1);
                    }
                } else {  // EPI == 2
                    const float* rp = resid + (long)m * ldc + n0;
                    *(float2*)(C + (long)m * ldc + n0) =
                        make_float2(v0 + rp[0], v1 + rp[1]);
                }
            }
        }
    }
}

// ---------------- LayerNorm + bf16 split (fused): one block per row --------
__global__ void __launch_bounds__(256) ln_split_kernel(
    const float* __restrict__ x, const float* __restrict__ g,
    const float* __restrict__ b, __nv_bfloat16* __restrict__ ah,
    __nv_bfloat16* __restrict__ al)
{
    int row = blockIdx.x;
    int tid = threadIdx.x;
    const float4* xr = (const float4*)(x + (long)row * Dq);
    float4 v = xr[tid];
    float s  = v.x + v.y + v.z + v.w;
    float sq = v.x*v.x + v.y*v.y + v.z*v.z + v.w*v.w;
    #pragma unroll
    for (int o = 16; o; o >>= 1) {
        s  += __shfl_xor_sync(0xffffffffu, s,  o);
        sq += __shfl_xor_sync(0xffffffffu, sq, o);
    }
    __shared__ float ss[8], ssq[8];
    if ((tid & 31) == 0) { ss[tid >> 5] = s; ssq[tid >> 5] = sq; }
    __syncthreads();
    float ts = 0.f, tq = 0.f;
    #pragma unroll
    for (int w = 0; w < 8; w++) { ts += ss[w]; tq += ssq[w]; }
    float mu  = ts * (1.f / Dq);
    float var = tq * (1.f / Dq) - mu * mu;
    float r   = rsqrtf(var + 1e-5f);
    float4 gg = ((const float4*)g)[tid];
    float4 bb = ((const float4*)b)[tid];
    float o0 = (v.x - mu) * r * gg.x + bb.x;
    float o1 = (v.y - mu) * r * gg.y + bb.y;
    float o2 = (v.z - mu) * r * gg.z + bb.z;
    float o3 = (v.w - mu) * r * gg.w + bb.w;
    __nv_bfloat16 h0, l0, h1, l1, h2, l2, h3, l3;
    split_bf16(o0, h0, l0); split_bf16(o1, h1, l1);
    split_bf16(o2, h2, l2); split_bf16(o3, h3, l3);
    long i2 = (long)row * (Dq / 2) + tid * 2;
    ((__nv_bfloat162*)ah)[i2]     = __halves2bfloat162(h0, h1);
    ((__nv_bfloat162*)ah)[i2 + 1] = __halves2bfloat162(h2, h3);
    ((__nv_bfloat162*)al)[i2]     = __halves2bfloat162(l0, l1);
    ((__nv_bfloat162*)al)[i2 + 1] = __halves2bfloat162(l2, l3);
}

// ---------------- Conv(K=4 causal) + SiLU + bf16 split ---------------------
// 4 timesteps per block via 7-row smem stage: tap loads per element 4 -> 1.75.
__global__ void __launch_bounds__(256) conv_silu_split(
    const float* __restrict__ xz, const float* __restrict__ w,
    const float* __restrict__ cb, float* __restrict__ xs,
    __nv_bfloat16* __restrict__ ah, __nv_bfloat16* __restrict__ al)
{
    __shared__ float sx[7][Dq];            // rows t0-3 .. t0+3 (x-half of xz)
    int blk = blockIdx.x;                  // b*(Tq/4) + t0/4
    int b   = blk >> 9;                    // / (Tq/4=512)
    int t0  = (blk & 511) * 4;
    int tid = threadIdx.x;
    int d0  = tid * 4;

    // stage 7 rows (zeros for t<0)
    #pragma unroll
    for (int p = 0; p < 7; p++) {
        int slot = tid + p * 256;          // 0..1791 over 7*256 slots
        int j = slot >> 8, c4 = (slot & 255) * 4;
        int t = t0 - 3 + j;
        float4 v = make_float4(0.f, 0.f, 0.f, 0.f);
        if (t >= 0)
            v = *(const float4*)(xz + ((long)(b * Tq + t)) * (2 * Dq) + c4);
        *(float4*)&sx[j][c4] = v;
    }
    __syncthreads();

    const float4* wp = (const float4*)(w + d0 * Kq);
    float4 w0 = wp[0], w1 = wp[1], w2 = wp[2], w3 = wp[3];
    float4 cbv = *(const float4*)(cb + d0);

    #pragma unroll
    for (int ts = 0; ts < 4; ts++) {
        float4 acc = cbv;
        #pragma unroll
        for (int k = 0; k < Kq; k++) {
            const float* srow = &sx[ts + k][d0];
            float t0w = (k == 0) ? w0.x : (k == 1) ? w0.y : (k == 2) ? w0.z : w0.w;
            float t1w = (k == 0) ? w1.x : (k == 1) ? w1.y : (k == 2) ? w1.z : w1.w;
            float t2w = (k == 0) ? w2.x : (k == 1) ? w2.y : (k == 2) ? w2.z : w2.w;
            float t3w = (k == 0) ? w3.x : (k == 1) ? w3.y : (k == 2) ? w3.z : w3.w;
            acc.x += t0w * srow[0];
            acc.y += t1w * srow[1];
            acc.z += t2w * srow[2];
            acc.w += t3w * srow[3];
        }
        float s0 = siluf(acc.x), s1 = siluf(acc.y);
        float s2 = siluf(acc.z), s3 = siluf(acc.w);

        long row = (long)(b * Tq + t0 + ts);
        *(float4*)(xs + row * Dq + d0) = make_float4(s0, s1, s2, s3);
        __nv_bfloat16 h0, l0, h1, l1, h2, l2, h3, l3;
        split_bf16(s0, h0, l0); split_bf16(s1, h1, l1);
        split_bf16(s2, h2, l2); split_bf16(s3, h3, l3);
        long i2 = row * (Dq / 2) + tid * 2;
        ((__nv_bfloat162*)ah)[i2]     = __halves2bfloat162(h0, h1);
        ((__nv_bfloat162*)ah)[i2 + 1] = __halves2bfloat162(h2, h3);
        ((__nv_bfloat162*)al)[i2]     = __halves2bfloat162(l0, l1);
        ((__nv_bfloat162*)al)[i2 + 1] = __halves2bfloat162(l2, l3);
    }
}

// ---------------- Chunked parallel selective scan ---------------------------
// Pass 1: local scan from h=0; emit end state, decay product, per-step decay
__global__ void __launch_bounds__(256) scan_pass1(
    const float* __restrict__ xs, const float* __restrict__ dt,
    const float* __restrict__ Bm, const float* __restrict__ negA,
    float* __restrict__ hend, float* __restrict__ Pp,
    float* __restrict__ decay)
{
    int blk = blockIdx.x;
    int b   = blk >> 8;
    int rem = blk & 255;
    int c   = rem >> 2;
    int d   = ((rem & 3) << 8) + threadIdx.x;
    float A = negA[d];

    __shared__ float Bs[Lq][DSq];
    for (int i = threadIdx.x; i < Lq * DSq; i += 256)
        Bs[i >> 4][i & 15] = Bm[((long)(b * Tq + c * Lq)) * DSq + i];
    __syncthreads();

    float h[DSq];
    #pragma unroll
    for (int s = 0; s < DSq; s++) h[s] = 0.f;
    float slog = 0.f;

    #pragma unroll 4
    for (int tt = 0; tt < Lq; tt++) {
        long row = (long)(b * Tq + c * Lq + tt);
        float xv  = xs[row * Dq + d];
        float dtv = dt[row * Dq + d];
        float e = fminf(dtv * A, 0.f);
        slog += e;
        float a = __expf(e);
        decay[row * Dq + d] = a;
        float u = dtv * xv;
        #pragma unroll
        for (int s = 0; s < DSq; s++) h[s] = h[s] * a + u * Bs[tt][s];
    }

    long base = (((long)(b * NCq + c)) * Dq + d) * DSq;
    #pragma unroll
    for (int s = 0; s < DSq; s++) hend[base + s] = h[s];
    Pp[((long)(b * NCq + c)) * Dq + d] = __expf(slog);
}

__global__ void __launch_bounds__(256) scan_pass2(
    const float* __restrict__ hend, const float* __restrict__ Pp,
    float* __restrict__ hstart)
{
    int idx = blockIdx.x * 256 + threadIdx.x;
    int s = idx & 15;
    int d = (idx >> 4) & (Dq - 1);
    int b = idx >> 14;
    float hs = 0.f;
    for (int c = 0; c < NCq; c++) {
        long base = (((long)(b * NCq + c)) * Dq + d) * DSq + s;
        hstart[base] = hs;
        float P = Pp[((long)(b * NCq + c)) * Dq + d];
        hs = P * hs + hend[base];
    }
}

// Pass 3: re-run chunk from known start using stored decay; gate; emit split y
__global__ void __launch_bounds__(256) scan_pass3(
    const float* __restrict__ xs, const float* __restrict__ dt,
    const float* __restrict__ Bm, const float* __restrict__ Cm,
    const float* __restrict__ decay, const float* __restrict__ Dp,
    const float* __restrict__ xz, const float* __restrict__ hstart,
    __nv_bfloat16* __restrict__ yh, __nv_bfloat16* __restrict__ yl)
{
    int blk = blockIdx.x;
    int b   = blk >> 8;
    int rem = blk & 255;
    int c   = rem >> 2;
    int d   = ((rem & 3) << 8) + threadIdx.x;
    float Dv = Dp[d];

    __shared__ float Bs[Lq][DSq];
    __shared__ float Cs[Lq][DSq];
    for (int i = threadIdx.x; i < Lq * DSq; i += 256) {
        Bs[i >> 4][i & 15] = Bm[((long)(b * Tq + c * Lq)) * DSq + i];
        Cs[i >> 4][i & 15] = Cm[((long)(b * Tq + c * Lq)) * DSq + i];
    }
    __syncthreads();

    float h[DSq];
    long base = (((long)(b * NCq + c)) * Dq + d) * DSq;
    #pragma unroll
    for (int s = 0; s < DSq; s++) h[s] = hstart[base + s];

    #pragma unroll 4
    for (int tt = 0; tt < Lq; tt++) {
        long row = (long)(b * Tq + c * Lq + tt);
        float xv  = xs[row * Dq + d];
        float dtv = dt[row * Dq + d];
        float a   = decay[row * Dq + d];
        float u = dtv * xv;
        float acc = 0.f;
        #pragma unroll
        for (int s = 0; s < DSq; s++) {
            h[s] = h[s] * a + u * Bs[tt][s];
            acc += h[s] * Cs[tt][s];
        }
        float zv = xz[row * (2 * Dq) + Dq + d];
        float yv = (acc + xv * Dv) * siluf(zv);
        __nv_bfloat16 hh, ll;
        split_bf16(yv, hh, ll);
        yh[row * Dq + d] = hh;
        yl[row * Dq + d] = ll;
    }
}

// ---------------- launch ----------------------------------------------------
extern "C" void kernel_launch(void* const* d_in, const int* in_sizes, int n_in,
                              void* d_out, int out_size)
{
    const float* x      = (const float*)d_in[0];
    const float* ln_g   = (const float*)d_in[1];
    const float* ln_b   = (const float*)d_in[2];
    const float* W_in   = (const float*)d_in[3];
    const float* conv_w = (const float*)d_in[4];
    const float* conv_b = (const float*)d_in[5];
    const float* dt_w   = (const float*)d_in[6];
    const float* dt_b   = (const float*)d_in[7];
    const float* B_w    = (const float*)d_in[8];
    const float* C_w    = (const float*)d_in[9];
    const float* log_A  = (const float*)d_in[10];
    const float* D_par  = (const float*)d_in[11];
    const float* W_out  = (const float*)d_in[12];
    float* out = (float*)d_out;

    float *xz, *xs, *dt, *dc, *Bm, *Cm, *he, *hs, *Pp, *nA;
    __nv_bfloat16 *ah, *al, *wh, *wl;
    cudaGetSymbolAddress((void**)&xz, g_xz);
    cudaGetSymbolAddress((void**)&xs, g_xs);
    cudaGetSymbolAddress((void**)&dt, g_dt);
    cudaGetSymbolAddress((void**)&dc, g_decay);
    cudaGetSymbolAddress((void**)&Bm, g_Bm);
    cudaGetSymbolAddress((void**)&Cm, g_Cm);
    cudaGetSymbolAddress((void**)&he, g_hend);
    cudaGetSymbolAddress((void**)&hs, g_hstart);
    cudaGetSymbolAddress((void**)&Pp, g_P);
    cudaGetSymbolAddress((void**)&nA, g_negA);
    cudaGetSymbolAddress((void**)&ah, g_ah);
    cudaGetSymbolAddress((void**)&al, g_al);
    cudaGetSymbolAddress((void**)&wh, g_wh);
    cudaGetSymbolAddress((void**)&wl, g_wl);

    cudaFuncSetAttribute(gemm_mma<0>, cudaFuncAttributeMaxDynamicSharedMemorySize, GSM_SZ);
    cudaFuncSetAttribute(gemm_mma<1>, cudaFuncAttributeMaxDynamicSharedMemorySize, GSM_SZ);
    cudaFuncSetAttribute(gemm_mma<2>, cudaFuncAttributeMaxDynamicSharedMemorySize, GSM_SZ);

    // 1. LayerNorm + bf16 split (fused)
    ln_split_kernel<<<ROWS, 256>>>(x, ln_g, ln_b, ah, al);

    // 2. xz = xn @ W_in   [4096,1024]x[1024,2048]
    convert_wt_kernel<<<dim3(2 * Dq / 32, Dq / 32), 256>>>(W_in, wh, wl, Dq, 2 * Dq);
    gemm_mma<0><<<dim3(2 * Dq / 128, ROWS / 256), 256, GSM_SZ>>>(
        ah, al, wh, wl, xz, ROWS, 2 * Dq, Dq, 2 * Dq, nullptr, nullptr,
        nullptr, nullptr);

    // 3. conv + silu + bf16 split (fused, 4 timesteps per block)
    conv_silu_split<<<ROWS / 4, 256>>>(xz, conv_w, conv_b, xs, ah, al);

    // 4. combined GEMM: [dt | Bm | Cm] = xs @ [dt_w | B_w | C_w] (N=1152)
    convert_wt_kernel<<<dim3(Dq / 32, Dq / 32), 256>>>(dt_w, wh, wl, Dq, Dq);
    bc_wt_kernel<<<(128 * Dq) / 256, 256>>>(B_w, C_w, log_A, wh, wl, nA);
    gemm_mma<1><<<dim3(NBC / 128, ROWS / 256), 256, GSM_SZ>>>(
        ah, al, wh, wl, dt, ROWS, NBC, Dq, Dq, dt_b, nullptr, Bm, Cm);

    // 5. chunked parallel selective scan + gate (emits split y)
    scan_pass1<<<Bq * NCq * (Dq / 256), 256>>>(xs, dt, Bm, nA, he, Pp, dc);
    scan_pass2<<<(Bq * Dq * DSq) / 256, 256>>>(he, Pp, hs);
    scan_pass3<<<Bq * NCq * (Dq / 256), 256>>>(xs, dt, Bm, Cm, dc, D_par,
                                               xz, hs, ah, al);

    // 6. out = residual + y @ W_out
    convert_wt_kernel<<<dim3(Dq / 32, Dq / 32), 256>>>(W_out, wh, wl, Dq, Dq);
    gemm_mma<2><<<dim3(Dq / 128, ROWS / 256), 256, GSM_SZ>>>(
        ah, al, wh, wl, out, ROWS, Dq, Dq, Dq, nullptr, x, nullptr, nullptr);
}